// round 1
// baseline (speedup 1.0000x reference)
#include <cuda_runtime.h>
#include <cstdint>

// ---------------------------------------------------------------------------
// GCNConv: out = X@H0 + A@(X@H1) + A^2@(X@H2)
// Restructured as:  out = Y0 + A@(Y1 + A@Y2), with [Y0|Y1|Y2] = X @ [H0|H1|H2]
//   -> one fused skinny GEMM + only TWO SpMM passes (instead of three).
// SpMM: warp-per-edge gather/scale + red.global.add.v4.f32 scatter.
// ---------------------------------------------------------------------------

#define N_NODES_MAX 100000
#define FDIM 128

// Scratch (allocation-free rule: device globals). 51.2 MB each.
__device__ float g_buf1[(size_t)N_NODES_MAX * FDIM];
__device__ float g_buf2[(size_t)N_NODES_MAX * FDIM];

// ---------------------------------------------------------------------------
// Fused GEMM: for k in {0,1,2}: dst_k = X @ H[k]   (X: [N,128], H[k]: [128,128])
// Classic 128x128 tile, BK=16, 256 threads, 8x8 per-thread microtile, fp32 FMA.
// blockIdx.x = row tile, blockIdx.y = k (selects destination).
// ---------------------------------------------------------------------------
__global__ __launch_bounds__(256, 2)
void gemm3_kernel(const float* __restrict__ X, const float* __restrict__ H,
                  float* __restrict__ out0, float* __restrict__ out1,
                  float* __restrict__ out2, int nN)
{
    const int kSel = blockIdx.y;
    float* dst = (kSel == 0) ? out0 : ((kSel == 1) ? out1 : out2);
    const float* Hk = H + (size_t)kSel * FDIM * FDIM;
    const int rowBase = blockIdx.x * 128;

    __shared__ float Xs[16][128 + 4];  // [kk][m], +4 pad keeps float4 alignment & spreads banks
    __shared__ float Hs[16][128];      // [kk][n]

    const int tid  = threadIdx.x;
    const int tRow = (tid >> 4) << 3;  // 0..120 step 8
    const int tCol = (tid & 15) << 3;  // 0..120 step 8

    float acc[8][8];
#pragma unroll
    for (int i = 0; i < 8; i++)
#pragma unroll
        for (int j = 0; j < 8; j++) acc[i][j] = 0.f;

    for (int k0 = 0; k0 < FDIM; k0 += 16) {
        // Load X tile: 128 rows x 16 k-cols = 512 float4, 2 per thread.
#pragma unroll
        for (int i = 0; i < 2; i++) {
            int id = tid + i * 256;
            int m  = id >> 2;           // row in tile
            int kk = (id & 3) << 2;     // 0,4,8,12
            float4 v = make_float4(0.f, 0.f, 0.f, 0.f);
            int gr = rowBase + m;
            if (gr < nN)
                v = *(const float4*)(X + (size_t)gr * FDIM + k0 + kk);
            Xs[kk + 0][m] = v.x;
            Xs[kk + 1][m] = v.y;
            Xs[kk + 2][m] = v.z;
            Xs[kk + 3][m] = v.w;
        }
        // Load H tile: 16 k-rows x 128 cols = 512 float4, 2 per thread.
#pragma unroll
        for (int i = 0; i < 2; i++) {
            int id = tid + i * 256;
            int kk = id >> 5;
            int c  = (id & 31) << 2;
            float4 v = *(const float4*)(Hk + (size_t)(k0 + kk) * FDIM + c);
            *(float4*)&Hs[kk][c] = v;
        }
        __syncthreads();

#pragma unroll
        for (int kk = 0; kk < 16; kk++) {
            float a[8], b[8];
            *(float4*)&a[0] = *(const float4*)&Xs[kk][tRow];
            *(float4*)&a[4] = *(const float4*)&Xs[kk][tRow + 4];
            *(float4*)&b[0] = *(const float4*)&Hs[kk][tCol];
            *(float4*)&b[4] = *(const float4*)&Hs[kk][tCol + 4];
#pragma unroll
            for (int i = 0; i < 8; i++)
#pragma unroll
                for (int j = 0; j < 8; j++)
                    acc[i][j] += a[i] * b[j];
        }
        __syncthreads();
    }

#pragma unroll
    for (int i = 0; i < 8; i++) {
        int gr = rowBase + tRow + i;
        if (gr < nN) {
            float* drow = dst + (size_t)gr * FDIM + tCol;
            *(float4*)(drow + 0) = make_float4(acc[i][0], acc[i][1], acc[i][2], acc[i][3]);
            *(float4*)(drow + 4) = make_float4(acc[i][4], acc[i][5], acc[i][6], acc[i][7]);
        }
    }
}

// ---------------------------------------------------------------------------
// SpMM: dst[row] += val * src[col]  for each edge. Warp per edge, lane per
// float4 (128 floats = 32 lanes x 4). Scatter with 16B vector reduction.
// dst must be pre-seeded with the additive term (Y1 / Y0).
// ---------------------------------------------------------------------------
__global__ __launch_bounds__(256)
void spmm_kernel(const int* __restrict__ rows, const int* __restrict__ cols,
                 const float* __restrict__ vals, const float* __restrict__ src,
                 float* __restrict__ dst, int nE)
{
    const int gtid = blockIdx.x * 256 + threadIdx.x;
    const int e    = gtid >> 5;
    if (e >= nE) return;
    const int lane = gtid & 31;

    const int   r = __ldg(rows + e);
    const int   c = __ldg(cols + e);
    const float v = __ldg(vals + e);

    float4 s = __ldg((const float4*)(src + (size_t)c * FDIM) + lane);
    float4 y = make_float4(s.x * v, s.y * v, s.z * v, s.w * v);

    float* d = dst + (size_t)r * FDIM + (lane << 2);
    asm volatile("red.global.add.v4.f32 [%0], {%1,%2,%3,%4};"
                 :: "l"(d), "f"(y.x), "f"(y.y), "f"(y.z), "f"(y.w)
                 : "memory");
}

// ---------------------------------------------------------------------------
extern "C" void kernel_launch(void* const* d_in, const int* in_sizes, int n_in,
                              void* d_out, int out_size)
{
    const int*   rows = (const int*)d_in[0];
    const int*   cols = (const int*)d_in[1];
    const float* vals = (const float*)d_in[2];
    const float* x    = (const float*)d_in[3];
    const float* H    = (const float*)d_in[4];
    float*       out  = (float*)d_out;

    const int nE = in_sizes[0];
    const int nN = in_sizes[3] / FDIM;

    float *buf1, *buf2;
    cudaGetSymbolAddress((void**)&buf1, g_buf1);
    cudaGetSymbolAddress((void**)&buf2, g_buf2);

    // [Y0|Y1|Y2] = X @ [H0|H1|H2]; Y0 -> out, Y1 -> buf1, Y2 -> buf2
    dim3 gGrid((nN + 127) / 128, 3, 1);
    gemm3_kernel<<<gGrid, 256>>>(x, H, out, buf1, buf2, nN);

    // buf1 = Y1 + A @ Y2
    const long long totalThreads = (long long)nE * 32;
    const int spmmBlocks = (int)((totalThreads + 255) / 256);
    spmm_kernel<<<spmmBlocks, 256>>>(rows, cols, vals, buf2, buf1, nE);

    // out = Y0 + A @ buf1
    spmm_kernel<<<spmmBlocks, 256>>>(rows, cols, vals, buf1, out, nE);
}

// round 2
// speedup vs baseline: 1.6937x; 1.6937x over previous
#include <cuda_runtime.h>
#include <cstdint>

// ---------------------------------------------------------------------------
// GCNConv: out = X@H0 + A@(X@H1) + A^2@(X@H2)
//   Restructured:  out = Y0 + A@(Y1 + A@Y2),  [Y0|Y1|Y2] = X @ [H0|H1|H2]
//   -> one fused GEMM + TWO SpMM passes.
// Round 2: build CSR per replay (hist/scan/scatter), then atomic-free SpMM
//   (warp-per-row, register accumulation) — removes 1.6GB of L2 atomics/pass.
// ---------------------------------------------------------------------------

#define N_NODES_MAX 100000
#define N_EDGES_MAX 3200000
#define FDIM 128

// Scratch (allocation-free rule: device globals).
__device__ float g_buf1[(size_t)N_NODES_MAX * FDIM];   // 51.2 MB
__device__ float g_buf2[(size_t)N_NODES_MAX * FDIM];   // 51.2 MB
__device__ int   g_rowptr[N_NODES_MAX + 1];
__device__ int   g_cursor[N_NODES_MAX + 1];
__device__ int2  g_ecv[N_EDGES_MAX];                   // 25.6 MB (col, val-bits)

// ---------------------------------------------------------------------------
// Fused GEMM: dst_k = X @ H[k], k in {0,1,2}. 128x128 tile, BK=16, 256 thr,
// 8x8 microtile, fp32.
// ---------------------------------------------------------------------------
__global__ __launch_bounds__(256, 2)
void gemm3_kernel(const float* __restrict__ X, const float* __restrict__ H,
                  float* __restrict__ out0, float* __restrict__ out1,
                  float* __restrict__ out2, int nN)
{
    const int kSel = blockIdx.y;
    float* dst = (kSel == 0) ? out0 : ((kSel == 1) ? out1 : out2);
    const float* Hk = H + (size_t)kSel * FDIM * FDIM;
    const int rowBase = blockIdx.x * 128;

    __shared__ float Xs[16][128 + 4];
    __shared__ float Hs[16][128];

    const int tid  = threadIdx.x;
    const int tRow = (tid >> 4) << 3;
    const int tCol = (tid & 15) << 3;

    float acc[8][8];
#pragma unroll
    for (int i = 0; i < 8; i++)
#pragma unroll
        for (int j = 0; j < 8; j++) acc[i][j] = 0.f;

    for (int k0 = 0; k0 < FDIM; k0 += 16) {
#pragma unroll
        for (int i = 0; i < 2; i++) {
            int id = tid + i * 256;
            int m  = id >> 2;
            int kk = (id & 3) << 2;
            float4 v = make_float4(0.f, 0.f, 0.f, 0.f);
            int gr = rowBase + m;
            if (gr < nN)
                v = *(const float4*)(X + (size_t)gr * FDIM + k0 + kk);
            Xs[kk + 0][m] = v.x;
            Xs[kk + 1][m] = v.y;
            Xs[kk + 2][m] = v.z;
            Xs[kk + 3][m] = v.w;
        }
#pragma unroll
        for (int i = 0; i < 2; i++) {
            int id = tid + i * 256;
            int kk = id >> 5;
            int c  = (id & 31) << 2;
            *(float4*)&Hs[kk][c] = *(const float4*)(Hk + (size_t)(k0 + kk) * FDIM + c);
        }
        __syncthreads();

#pragma unroll
        for (int kk = 0; kk < 16; kk++) {
            float a[8], b[8];
            *(float4*)&a[0] = *(const float4*)&Xs[kk][tRow];
            *(float4*)&a[4] = *(const float4*)&Xs[kk][tRow + 4];
            *(float4*)&b[0] = *(const float4*)&Hs[kk][tCol];
            *(float4*)&b[4] = *(const float4*)&Hs[kk][tCol + 4];
#pragma unroll
            for (int i = 0; i < 8; i++)
#pragma unroll
                for (int j = 0; j < 8; j++)
                    acc[i][j] += a[i] * b[j];
        }
        __syncthreads();
    }

#pragma unroll
    for (int i = 0; i < 8; i++) {
        int gr = rowBase + tRow + i;
        if (gr < nN) {
            float* drow = dst + (size_t)gr * FDIM + tCol;
            *(float4*)(drow + 0) = make_float4(acc[i][0], acc[i][1], acc[i][2], acc[i][3]);
            *(float4*)(drow + 4) = make_float4(acc[i][4], acc[i][5], acc[i][6], acc[i][7]);
        }
    }
}

// ---------------------------------------------------------------------------
// CSR build: zero histogram -> histogram -> single-block scan -> scatter
// ---------------------------------------------------------------------------
__global__ void zero_kernel(int* __restrict__ p, int n)
{
    int i = blockIdx.x * 256 + threadIdx.x;
    if (i < n) p[i] = 0;
}

__global__ void hist_kernel(const int* __restrict__ rows, int* __restrict__ cnt, int nE)
{
    int e = blockIdx.x * 256 + threadIdx.x;
    if (e < nE) atomicAdd(&cnt[rows[e]], 1);
}

// Exclusive scan over cnt[0..nN) -> rowptr[0..nN], rowptr[nN] = total.
// One block, 1024 threads, chunked.
__global__ __launch_bounds__(1024)
void scan_kernel(const int* __restrict__ cnt, int* __restrict__ rowptr, int nN)
{
    __shared__ int sh[1024];
    const int t   = threadIdx.x;
    const int per = (nN + 1023) >> 10;
    const int b   = min(t * per, nN);
    const int e   = min(b + per, nN);

    int s = 0;
    for (int i = b; i < e; i++) s += cnt[i];
    sh[t] = s;
    __syncthreads();

    for (int off = 1; off < 1024; off <<= 1) {
        int add = (t >= off) ? sh[t - off] : 0;
        __syncthreads();
        sh[t] += add;
        __syncthreads();
    }

    int run = sh[t] - s;  // exclusive prefix of this chunk
    for (int i = b; i < e; i++) { rowptr[i] = run; run += cnt[i]; }
    if (t == 1023) rowptr[nN] = sh[1023];
}

__global__ void copy_cursor_kernel(const int* __restrict__ rowptr,
                                   int* __restrict__ cursor, int nN)
{
    int i = blockIdx.x * 256 + threadIdx.x;
    if (i < nN) cursor[i] = rowptr[i];
}

__global__ void scatter_kernel(const int* __restrict__ rows, const int* __restrict__ cols,
                               const float* __restrict__ vals, int* __restrict__ cursor,
                               int2* __restrict__ ecv, int nE)
{
    int e = blockIdx.x * 256 + threadIdx.x;
    if (e < nE) {
        int r   = rows[e];
        int pos = atomicAdd(&cursor[r], 1);
        ecv[pos] = make_int2(cols[e], __float_as_int(vals[e]));
    }
}

// ---------------------------------------------------------------------------
// SpMM (CSR): warp per dest row, register accumulation, NO atomics.
// dst pre-seeded with the additive term; dst[row] += sum_e v_e * src[col_e].
// ---------------------------------------------------------------------------
__global__ __launch_bounds__(256)
void spmm_csr_kernel(const int* __restrict__ rowptr, const int2* __restrict__ ecv,
                     const float* __restrict__ src, float* __restrict__ dst, int nN)
{
    const int w = (blockIdx.x * 256 + threadIdx.x) >> 5;
    if (w >= nN) return;
    const int lane  = threadIdx.x & 31;
    const int start = __ldg(rowptr + w);
    const int end   = __ldg(rowptr + w + 1);

    float4 acc = make_float4(0.f, 0.f, 0.f, 0.f);

#pragma unroll 4
    for (int i = start; i < end; i++) {
        int2  cv = __ldg(ecv + i);               // warp-uniform 8B load (L1 broadcast)
        float v  = __int_as_float(cv.y);
        float4 s = __ldg((const float4*)(src + (size_t)cv.x * FDIM) + lane);
        acc.x += v * s.x;
        acc.y += v * s.y;
        acc.z += v * s.z;
        acc.w += v * s.w;
    }

    float4* d  = (float4*)(dst + (size_t)w * FDIM) + lane;
    float4 cur = *d;
    cur.x += acc.x; cur.y += acc.y; cur.z += acc.z; cur.w += acc.w;
    *d = cur;
}

// ---------------------------------------------------------------------------
extern "C" void kernel_launch(void* const* d_in, const int* in_sizes, int n_in,
                              void* d_out, int out_size)
{
    const int*   rows = (const int*)d_in[0];
    const int*   cols = (const int*)d_in[1];
    const float* vals = (const float*)d_in[2];
    const float* x    = (const float*)d_in[3];
    const float* H    = (const float*)d_in[4];
    float*       out  = (float*)d_out;

    const int nE = in_sizes[0];
    const int nN = in_sizes[3] / FDIM;

    float *buf1, *buf2;
    int *rowptr, *cursor;
    int2 *ecv;
    cudaGetSymbolAddress((void**)&buf1, g_buf1);
    cudaGetSymbolAddress((void**)&buf2, g_buf2);
    cudaGetSymbolAddress((void**)&rowptr, g_rowptr);
    cudaGetSymbolAddress((void**)&cursor, g_cursor);
    cudaGetSymbolAddress((void**)&ecv, g_ecv);

    const int eBlocks = (nE + 255) / 256;
    const int nBlocks = (nN + 255) / 256;

    // [Y0|Y1|Y2] = X @ [H0|H1|H2]; Y0 -> out, Y1 -> buf1, Y2 -> buf2
    dim3 gGrid((nN + 127) / 128, 3, 1);
    gemm3_kernel<<<gGrid, 256>>>(x, H, out, buf1, buf2, nN);

    // CSR build (cursor doubles as the histogram buffer first)
    zero_kernel<<<nBlocks, 256>>>(cursor, nN);
    hist_kernel<<<eBlocks, 256>>>(rows, cursor, nE);
    scan_kernel<<<1, 1024>>>(cursor, rowptr, nN);
    copy_cursor_kernel<<<nBlocks, 256>>>(rowptr, cursor, nN);
    scatter_kernel<<<eBlocks, 256>>>(rows, cols, vals, cursor, ecv, nE);

    // Two atomic-free SpMM passes
    const int spmmBlocks = (int)(((long long)nN * 32 + 255) / 256);
    spmm_csr_kernel<<<spmmBlocks, 256>>>(rowptr, ecv, buf2, buf1, nN);  // buf1 = Y1 + A@Y2
    spmm_csr_kernel<<<spmmBlocks, 256>>>(rowptr, ecv, buf1, out, nN);   // out  = Y0 + A@buf1
}

// round 3
// speedup vs baseline: 2.0574x; 1.2147x over previous
#include <cuda_runtime.h>
#include <cstdint>

// ---------------------------------------------------------------------------
// GCNConv: out = X@H0 + A@(X@H1) + A^2@(X@H2)
//   Restructured:  out = Y0 + A@(Y1 + A@Y2),  [Y0|Y1|Y2] = X @ [H0|H1|H2]
// Round 3: parallel 3-phase scan (was 94us single-block) + fork-join stream
//   overlap of CSR build with the GEMM.
// ---------------------------------------------------------------------------

#define N_NODES_MAX 100000
#define N_EDGES_MAX 3200000
#define FDIM 128

__device__ float g_buf1[(size_t)N_NODES_MAX * FDIM];
__device__ float g_buf2[(size_t)N_NODES_MAX * FDIM];
__device__ int   g_rowptr[N_NODES_MAX + 1];
__device__ int   g_cursor[N_NODES_MAX + 1];
__device__ int   g_bsum[1024];
__device__ int2  g_ecv[N_EDGES_MAX];

// ---------------------------------------------------------------------------
// Fused GEMM: dst_k = X @ H[k], k in {0,1,2}.
// ---------------------------------------------------------------------------
__global__ __launch_bounds__(256, 2)
void gemm3_kernel(const float* __restrict__ X, const float* __restrict__ H,
                  float* __restrict__ out0, float* __restrict__ out1,
                  float* __restrict__ out2, int nN)
{
    const int kSel = blockIdx.y;
    float* dst = (kSel == 0) ? out0 : ((kSel == 1) ? out1 : out2);
    const float* Hk = H + (size_t)kSel * FDIM * FDIM;
    const int rowBase = blockIdx.x * 128;

    __shared__ float Xs[16][128 + 4];
    __shared__ float Hs[16][128];

    const int tid  = threadIdx.x;
    const int tRow = (tid >> 4) << 3;
    const int tCol = (tid & 15) << 3;

    float acc[8][8];
#pragma unroll
    for (int i = 0; i < 8; i++)
#pragma unroll
        for (int j = 0; j < 8; j++) acc[i][j] = 0.f;

    for (int k0 = 0; k0 < FDIM; k0 += 16) {
#pragma unroll
        for (int i = 0; i < 2; i++) {
            int id = tid + i * 256;
            int m  = id >> 2;
            int kk = (id & 3) << 2;
            float4 v = make_float4(0.f, 0.f, 0.f, 0.f);
            int gr = rowBase + m;
            if (gr < nN)
                v = *(const float4*)(X + (size_t)gr * FDIM + k0 + kk);
            Xs[kk + 0][m] = v.x;
            Xs[kk + 1][m] = v.y;
            Xs[kk + 2][m] = v.z;
            Xs[kk + 3][m] = v.w;
        }
#pragma unroll
        for (int i = 0; i < 2; i++) {
            int id = tid + i * 256;
            int kk = id >> 5;
            int c  = (id & 31) << 2;
            *(float4*)&Hs[kk][c] = *(const float4*)(Hk + (size_t)(k0 + kk) * FDIM + c);
        }
        __syncthreads();

#pragma unroll
        for (int kk = 0; kk < 16; kk++) {
            float a[8], b[8];
            *(float4*)&a[0] = *(const float4*)&Xs[kk][tRow];
            *(float4*)&a[4] = *(const float4*)&Xs[kk][tRow + 4];
            *(float4*)&b[0] = *(const float4*)&Hs[kk][tCol];
            *(float4*)&b[4] = *(const float4*)&Hs[kk][tCol + 4];
#pragma unroll
            for (int i = 0; i < 8; i++)
#pragma unroll
                for (int j = 0; j < 8; j++)
                    acc[i][j] += a[i] * b[j];
        }
        __syncthreads();
    }

#pragma unroll
    for (int i = 0; i < 8; i++) {
        int gr = rowBase + tRow + i;
        if (gr < nN) {
            float* drow = dst + (size_t)gr * FDIM + tCol;
            *(float4*)(drow + 0) = make_float4(acc[i][0], acc[i][1], acc[i][2], acc[i][3]);
            *(float4*)(drow + 4) = make_float4(acc[i][4], acc[i][5], acc[i][6], acc[i][7]);
        }
    }
}

// ---------------------------------------------------------------------------
// CSR build
// ---------------------------------------------------------------------------
__global__ void hist_kernel(const int* __restrict__ rows, int* __restrict__ cnt, int nE)
{
    int e = blockIdx.x * 256 + threadIdx.x;
    if (e < nE) atomicAdd(&cnt[rows[e]], 1);
}

// Phase 1: per-block scan of 1024 counts (256 thr x 4). Writes exclusive
// partial prefixes into pre[] and the block total into bsum[].
__global__ __launch_bounds__(256)
void scan1_kernel(const int* __restrict__ cnt, int* __restrict__ pre,
                  int* __restrict__ bsum, int nN)
{
    const int t    = threadIdx.x;
    const int base = blockIdx.x * 1024 + t * 4;
    const int lane = t & 31, warp = t >> 5;

    int v[4];
#pragma unroll
    for (int j = 0; j < 4; j++) v[j] = (base + j < nN) ? cnt[base + j] : 0;
    const int s = v[0] + v[1] + v[2] + v[3];

    // inclusive warp scan of s
    int incl = s;
#pragma unroll
    for (int off = 1; off < 32; off <<= 1) {
        int n = __shfl_up_sync(0xFFFFFFFFu, incl, off);
        if (lane >= off) incl += n;
    }

    __shared__ int wsum[8];
    if (lane == 31) wsum[warp] = incl;
    __syncthreads();
    if (t < 8) {
        int w = wsum[t];
        int wincl = w;
#pragma unroll
        for (int off = 1; off < 8; off <<= 1) {
            int n = __shfl_up_sync(0xFFu, wincl, off);
            if (t >= off) wincl += n;
        }
        wsum[t] = wincl - w;  // exclusive
    }
    __syncthreads();

    int run = incl - s + wsum[warp];  // exclusive prefix of this thread's group
#pragma unroll
    for (int j = 0; j < 4; j++) {
        if (base + j < nN) pre[base + j] = run;
        run += v[j];
    }
    if (t == 255) bsum[blockIdx.x] = run;  // block total
}

// Phase 2: scan the (<=1024) block sums; write grand total to rowptr[nN].
__global__ __launch_bounds__(1024)
void scan2_kernel(int* __restrict__ bsum, int* __restrict__ total_out, int B)
{
    __shared__ int sh[1024];
    const int t = threadIdx.x;
    int v = (t < B) ? bsum[t] : 0;
    sh[t] = v;
    __syncthreads();
    for (int off = 1; off < 1024; off <<= 1) {
        int a = (t >= off) ? sh[t - off] : 0;
        __syncthreads();
        sh[t] += a;
        __syncthreads();
    }
    if (t < B) bsum[t] = sh[t] - v;      // exclusive
    if (t == 1023) *total_out = sh[1023];
}

// Phase 3: finalize rowptr (+block offset) and seed cursor in one pass.
__global__ void scan3_kernel(int* __restrict__ rowptr, const int* __restrict__ bsum,
                             int* __restrict__ cursor, int nN)
{
    int i = blockIdx.x * 256 + threadIdx.x;
    if (i < nN) {
        int val = rowptr[i] + __ldg(bsum + (i >> 10));
        rowptr[i] = val;
        cursor[i] = val;
    }
}

__global__ void scatter_kernel(const int* __restrict__ rows, const int* __restrict__ cols,
                               const float* __restrict__ vals, int* __restrict__ cursor,
                               int2* __restrict__ ecv, int nE)
{
    int e = blockIdx.x * 256 + threadIdx.x;
    if (e < nE) {
        int r   = rows[e];
        int pos = atomicAdd(&cursor[r], 1);
        ecv[pos] = make_int2(cols[e], __float_as_int(vals[e]));
    }
}

// ---------------------------------------------------------------------------
// SpMM (CSR): warp per dest row, register accumulation, NO atomics.
// ---------------------------------------------------------------------------
__global__ __launch_bounds__(256)
void spmm_csr_kernel(const int* __restrict__ rowptr, const int2* __restrict__ ecv,
                     const float* __restrict__ src, float* __restrict__ dst, int nN)
{
    const int w = (blockIdx.x * 256 + threadIdx.x) >> 5;
    if (w >= nN) return;
    const int lane  = threadIdx.x & 31;
    const int start = __ldg(rowptr + w);
    const int end   = __ldg(rowptr + w + 1);

    float4 acc = make_float4(0.f, 0.f, 0.f, 0.f);

#pragma unroll 4
    for (int i = start; i < end; i++) {
        int2  cv = __ldg(ecv + i);
        float v  = __int_as_float(cv.y);
        float4 s = __ldg((const float4*)(src + (size_t)cv.x * FDIM) + lane);
        acc.x += v * s.x;
        acc.y += v * s.y;
        acc.z += v * s.z;
        acc.w += v * s.w;
    }

    float4* d  = (float4*)(dst + (size_t)w * FDIM) + lane;
    float4 cur = *d;
    cur.x += acc.x; cur.y += acc.y; cur.z += acc.z; cur.w += acc.w;
    *d = cur;
}

// ---------------------------------------------------------------------------
extern "C" void kernel_launch(void* const* d_in, const int* in_sizes, int n_in,
                              void* d_out, int out_size)
{
    const int*   rows = (const int*)d_in[0];
    const int*   cols = (const int*)d_in[1];
    const float* vals = (const float*)d_in[2];
    const float* x    = (const float*)d_in[3];
    const float* H    = (const float*)d_in[4];
    float*       out  = (float*)d_out;

    const int nE = in_sizes[0];
    const int nN = in_sizes[3] / FDIM;

    float *buf1, *buf2;
    int *rowptr, *cursor, *bsum;
    int2 *ecv;
    cudaGetSymbolAddress((void**)&buf1, g_buf1);
    cudaGetSymbolAddress((void**)&buf2, g_buf2);
    cudaGetSymbolAddress((void**)&rowptr, g_rowptr);
    cudaGetSymbolAddress((void**)&cursor, g_cursor);
    cudaGetSymbolAddress((void**)&bsum, g_bsum);
    cudaGetSymbolAddress((void**)&ecv, g_ecv);

    // Lazily created side stream + events for fork-join inside graph capture.
    static cudaStream_t sGemm = nullptr;
    static cudaEvent_t  evFork = nullptr, evGemm = nullptr;
    if (sGemm == nullptr) {
        cudaStreamCreateWithFlags(&sGemm, cudaStreamNonBlocking);
        cudaEventCreateWithFlags(&evFork, cudaEventDisableTiming);
        cudaEventCreateWithFlags(&evGemm, cudaEventDisableTiming);
    }

    const int eBlocks = (nE + 255) / 256;
    const int nBlocks = (nN + 255) / 256;
    const int B       = (nN + 1023) / 1024;  // scan1 blocks

    // ---- fork: GEMM on side stream ----
    cudaEventRecord(evFork, 0);
    cudaStreamWaitEvent(sGemm, evFork, 0);
    dim3 gGrid((nN + 127) / 128, 3, 1);
    gemm3_kernel<<<gGrid, 256, 0, sGemm>>>(x, H, out, buf1, buf2, nN);
    cudaEventRecord(evGemm, sGemm);

    // ---- CSR build on main stream (overlaps with GEMM) ----
    cudaMemsetAsync(cursor, 0, (size_t)nN * sizeof(int), 0);
    hist_kernel<<<eBlocks, 256>>>(rows, cursor, nE);
    scan1_kernel<<<B, 256>>>(cursor, rowptr, bsum, nN);     // rowptr <- partial prefixes
    scan2_kernel<<<1, 1024>>>(bsum, rowptr + nN, B);
    scan3_kernel<<<nBlocks, 256>>>(rowptr, bsum, cursor, nN);
    scatter_kernel<<<eBlocks, 256>>>(rows, cols, vals, cursor, ecv, nE);

    // ---- join, then two atomic-free SpMM passes ----
    cudaStreamWaitEvent(0, evGemm, 0);
    const int spmmBlocks = (int)(((long long)nN * 32 + 255) / 256);
    spmm_csr_kernel<<<spmmBlocks, 256>>>(rowptr, ecv, buf2, buf1, nN);  // buf1 = Y1 + A@Y2
    spmm_csr_kernel<<<spmmBlocks, 256>>>(rowptr, ecv, buf1, out, nN);   // out  = Y0 + A@buf1
}